// round 1
// baseline (speedup 1.0000x reference)
#include <cuda_runtime.h>
#include <math.h>

// Problem constants: sat/grd [32, 64, 64, 64] float32
#define BS 32          // batch (both sat and grd)
#define NF 33          // rfft bins for length-64 axis
#define KDIM 4096      // 64*64 reduction dim (c,w) or (c,h)
#define SATN (32*64*64*64)   // 8388608 elements per tensor

// -------- device scratch (static, allocation-free) --------
__device__ float2 g_Sh[(size_t)NF * BS * KDIM];   // DFT over h of sat, k=(c,w)
__device__ float2 g_Gh[(size_t)NF * BS * KDIM];   // DFT over h of grd (w-flipped), k=(c,w)
__device__ float2 g_Sw[(size_t)NF * BS * KDIM];   // DFT over w of sat, k=(c,h)
__device__ float2 g_Gw[(size_t)NF * BS * KDIM];   // DFT over w of grd, k=(c,h)
__device__ float2 g_CpH[8 * NF * BS * BS];        // partial freq-GEMM (corr)
__device__ float2 g_CpW[8 * NF * BS * BS];        // partial freq-GEMM (dot)
__device__ float2 g_tw[NF * 64];                  // tw[f][n] = (cos,sin)(2*pi*f*n/64)
__device__ int    g_orien[BS * BS];
__device__ float  g_norm[BS];

// -------- twiddle init --------
__global__ void k_init() {
    int idx = blockIdx.x * blockDim.x + threadIdx.x;
    if (idx < NF * 64) {
        int f = idx >> 6, n = idx & 63;
        // angle = 2*pi*f*n/64 ; sincospif(x) = sin/cos(pi*x), x = (f*n mod 64)/32 in [0,2)
        float x = (float)((f * n) & 63) / 32.0f;
        float s, c;
        sincospif(x, &s, &c);
        g_tw[idx] = make_float2(c, s);
    }
}

// -------- DFT along one axis of each [64h x 64w] slab --------
// grid = 2048 blocks (i*64 + c), 256 threads.
// axisH=1: transform over h, output column index = w (optionally w-flipped input)
// axisH=0: transform over w, output column index = h
__global__ void k_dft(const float* __restrict__ src, int sel, int axisH, int flip) {
    __shared__ float  slab[64 * 65];
    __shared__ float2 stw[NF * 64];
    float2* dst = (sel == 0) ? g_Sh : (sel == 1) ? g_Gh : (sel == 2) ? g_Sw : g_Gw;

    int b = blockIdx.x;            // i*64 + c
    int tid = threadIdx.x;
    const float* p = src + (size_t)b * 4096;

#pragma unroll
    for (int t = 0; t < 16; t++) {
        int idx = tid + t * 256;
        slab[(idx >> 6) * 65 + (idx & 63)] = p[idx];
    }
    for (int t = tid; t < NF * 64; t += 256) stw[t] = g_tw[t];
    __syncthreads();

    int col = tid & 63;
    int m   = tid >> 6;            // 0..3 -> freq groups f = m, m+4, ...
    float v[64];
    if (axisH) {
        int cc = flip ? (63 - col) : col;
#pragma unroll
        for (int n = 0; n < 64; n++) v[n] = slab[n * 65 + cc];
    } else {
#pragma unroll
        for (int n = 0; n < 64; n++) v[n] = slab[col * 65 + n];
    }

    int i = b >> 6, c = b & 63;
    for (int f = m; f < NF; f += 4) {
        float ar = 0.f, ai = 0.f;
        const float2* twf = &stw[f * 64];
#pragma unroll
        for (int n = 0; n < 64; n++) {
            float2 t = twf[n];
            ar = fmaf(v[n],  t.x, ar);
            ai = fmaf(v[n], -t.y, ai);
        }
        dst[((size_t)f * BS + i) * KDIM + c * 64 + col] = make_float2(ar, ai);
    }
}

// -------- per-frequency complex GEMM: C[f][i][j] = sum_k S[f][i][k] * conj(G[f][j][k]) --------
// grid = 33 freqs * 8 k-chunks = 264 blocks, 256 threads; each thread does a 2x2 (i,j) tile.
__global__ void k_fgemm(int sel) {
    __shared__ float2 sS[64 * 33];
    __shared__ float2 sG[64 * 33];
    const float2* S = sel ? g_Sw : g_Sh;
    const float2* G = sel ? g_Gw : g_Gh;
    float2* Cp      = sel ? g_CpW : g_CpH;

    int f  = blockIdx.x >> 3;
    int kc = blockIdx.x & 7;
    int tid = threadIdx.x;
    int li = tid >> 3;             // 0..31 row for staging
    int ls = tid & 7;
    int i0 = (tid >> 4) * 2;       // 0..30
    int j0 = (tid & 15) * 2;       // 0..30

    float c00r = 0, c00i = 0, c01r = 0, c01i = 0;
    float c10r = 0, c10i = 0, c11r = 0, c11i = 0;

    const float2* Sb = S + (size_t)f * BS * KDIM + kc * 512;
    const float2* Gb = G + (size_t)f * BS * KDIM + kc * 512;

    for (int kt = 0; kt < 8; kt++) {
        __syncthreads();
#pragma unroll
        for (int u = 0; u < 8; u++) {
            int k = ls + u * 8;
            sS[k * 33 + li] = Sb[(size_t)li * KDIM + kt * 64 + k];
            sG[k * 33 + li] = Gb[(size_t)li * KDIM + kt * 64 + k];
        }
        __syncthreads();
#pragma unroll 8
        for (int k = 0; k < 64; k++) {
            float2 a0 = sS[k * 33 + i0];
            float2 a1 = sS[k * 33 + i0 + 1];
            float2 b0 = sG[k * 33 + j0];
            float2 b1 = sG[k * 33 + j0 + 1];
            c00r += a0.x * b0.x + a0.y * b0.y;  c00i += a0.y * b0.x - a0.x * b0.y;
            c01r += a0.x * b1.x + a0.y * b1.y;  c01i += a0.y * b1.x - a0.x * b1.y;
            c10r += a1.x * b0.x + a1.y * b0.y;  c10i += a1.y * b0.x - a1.x * b0.y;
            c11r += a1.x * b1.x + a1.y * b1.y;  c11i += a1.y * b1.x - a1.x * b1.y;
        }
    }
    float2* outp = Cp + ((size_t)kc * NF + f) * BS * BS;
    outp[i0 * 32 + j0]           = make_float2(c00r, c00i);
    outp[i0 * 32 + j0 + 1]       = make_float2(c01r, c01i);
    outp[(i0 + 1) * 32 + j0]     = make_float2(c10r, c10i);
    outp[(i0 + 1) * 32 + j0 + 1] = make_float2(c11r, c11i);
}

// -------- inverse rfft over 64 shifts + first-max argmax (corr phase) --------
// grid 32 (i), 32 threads (j)
__global__ void k_corr_inv(float* __restrict__ out_orien_f) {
    int i = blockIdx.x, j = threadIdx.x;
    float2 C[NF];
#pragma unroll
    for (int f = 0; f < NF; f++) {
        float xr = 0.f, xi = 0.f;
#pragma unroll
        for (int kc = 0; kc < 8; kc++) {
            float2 v = g_CpH[((kc * NF + f) * BS + i) * BS + j];
            xr += v.x; xi += v.y;
        }
        C[f] = make_float2(xr, xi);
    }
    float best = -3.4e38f;
    int bests = 0;
    for (int s = 0; s < 64; s++) {
        float acc = C[0].x + ((s & 1) ? -C[32].x : C[32].x);
        for (int f = 1; f < 32; f++) {
            float2 t = g_tw[f * 64 + s];           // angle 2*pi*f*s/64
            acc += 2.f * (C[f].x * t.x - C[f].y * t.y);
        }
        acc *= (1.f / 64.f);
        if (acc > best) { best = acc; bests = s; } // first max (jnp.argmax semantics)
    }
    g_orien[i * 32 + j] = bests;
    out_orien_f[i * 32 + j] = (float)bests;
}

// -------- per-sat L2 norm --------
__global__ void k_norm(const float* __restrict__ sat) {
    __shared__ float red[256];
    int i = blockIdx.x;
    const float* p = sat + (size_t)i * 262144;
    float s = 0.f;
    for (int t = threadIdx.x; t < 262144; t += 256) { float v = p[t]; s = fmaf(v, v, s); }
    red[threadIdx.x] = s;
    __syncthreads();
    for (int o = 128; o > 0; o >>= 1) {
        if (threadIdx.x < o) red[threadIdx.x] += red[threadIdx.x + o];
        __syncthreads();
    }
    if (threadIdx.x == 0) g_norm[i] = sqrtf(red[0] + 1e-8f);
}

// -------- evaluate dot at the chosen shift, emit distance[j][i] --------
__global__ void k_dot_inv(float* __restrict__ out_dist) {
    int i = blockIdx.x, j = threadIdx.x;
    float2 C[NF];
#pragma unroll
    for (int f = 0; f < NF; f++) {
        float xr = 0.f, xi = 0.f;
#pragma unroll
        for (int kc = 0; kc < 8; kc++) {
            float2 v = g_CpW[((kc * NF + f) * BS + i) * BS + j];
            xr += v.x; xi += v.y;
        }
        C[f] = make_float2(xr, xi);
    }
    int o = g_orien[i * 32 + j];
    float q = C[0].x + ((o & 1) ? -C[32].x : C[32].x);
#pragma unroll
    for (int f = 1; f < 32; f++) {
        float2 t = g_tw[f * 64 + o];
        q += 2.f * (C[f].x * t.x - C[f].y * t.y);
    }
    q *= (1.f / 64.f);
    float dot = q / g_norm[i];
    out_dist[j * 32 + i] = 2.f - 2.f * dot;     // distance = 2 - 2*dot.T
}

extern "C" void kernel_launch(void* const* d_in, const int* in_sizes, int n_in,
                              void* d_out, int out_size) {
    (void)in_sizes; (void)n_in; (void)out_size;
    const float* sat = (const float*)d_in[0];
    const float* grd = (const float*)d_in[1];
    float* out = (float*)d_out;

    // Passthrough copies: out = [sat | grd | distance(32x32) | orien(32x32)]
    cudaMemcpyAsync(out, sat, (size_t)SATN * sizeof(float), cudaMemcpyDeviceToDevice);
    cudaMemcpyAsync(out + SATN, grd, (size_t)SATN * sizeof(float), cudaMemcpyDeviceToDevice);

    k_init<<<9, 256>>>();

    // Forward DFTs: corr axis = height (grd width-flipped), dot axis = width
    k_dft<<<2048, 256>>>(sat, 0, 1, 0);   // g_Sh
    k_dft<<<2048, 256>>>(grd, 1, 1, 1);   // g_Gh (w-flipped)
    k_dft<<<2048, 256>>>(sat, 2, 0, 0);   // g_Sw
    k_dft<<<2048, 256>>>(grd, 3, 0, 0);   // g_Gw

    // Per-frequency 32x32 complex GEMMs, K = 4096, split into 8 k-chunks (deterministic partials)
    k_fgemm<<<264, 256>>>(0);             // corr (h-axis)
    k_fgemm<<<264, 256>>>(1);             // dot  (w-axis)

    k_norm<<<32, 256>>>(sat);

    float* out_dist  = out + (size_t)2 * SATN;
    float* out_orien = out + (size_t)2 * SATN + 1024;
    k_corr_inv<<<32, 32>>>(out_orien);
    k_dot_inv<<<32, 32>>>(out_dist);
}

// round 3
// speedup vs baseline: 1.1531x; 1.1531x over previous
#include <cuda_runtime.h>
#include <math.h>

#define BS 32
#define NF 33
#define KDIM 4096
#define SATN (32*64*64*64)
#define NKC 4            // k-chunks per freq in fgemm

// -------- device scratch --------
__device__ float2 g_Sh[(size_t)NF * BS * KDIM];
__device__ float2 g_Gh[(size_t)NF * BS * KDIM];
__device__ float2 g_Sw[(size_t)NF * BS * KDIM];
__device__ float2 g_Gw[(size_t)NF * BS * KDIM];
__device__ float2 g_CpH[NKC * NF * BS * BS];
__device__ float2 g_CpW[NKC * NF * BS * BS];
__device__ float2 g_tw[NF * 64];
__device__ float  g_norm[BS];

// -------- twiddle init: g_tw[f*64+n] = (cos,sin)(2*pi*f*n/64) --------
__global__ void k_init() {
    int idx = blockIdx.x * blockDim.x + threadIdx.x;
    if (idx < NF * 64) {
        int f = idx >> 6, n = idx & 63;
        float x = (float)((f * n) & 63) / 32.0f;
        float s, c;
        sincospif(x, &s, &c);
        g_tw[idx] = make_float2(c, s);
    }
}

// -------- DFT along one axis of each [64h x 64w] slab (R1-verbatim, proven) --------
// grid = 2048 blocks (i*64 + c), 256 threads.
// axisH=1: transform over h, output column index = w (optionally w-flipped input)
// axisH=0: transform over w, output column index = h
__global__ void k_dft(const float* __restrict__ src, int sel, int axisH, int flip) {
    __shared__ float  slab[64 * 65];
    __shared__ float2 stw[NF * 64];
    float2* dst = (sel == 0) ? g_Sh : (sel == 1) ? g_Gh : (sel == 2) ? g_Sw : g_Gw;

    int b = blockIdx.x;            // i*64 + c
    int tid = threadIdx.x;
    const float* p = src + (size_t)b * 4096;

#pragma unroll
    for (int t = 0; t < 16; t++) {
        int idx = tid + t * 256;
        slab[(idx >> 6) * 65 + (idx & 63)] = p[idx];
    }
    for (int t = tid; t < NF * 64; t += 256) stw[t] = g_tw[t];
    __syncthreads();

    int col = tid & 63;
    int m   = tid >> 6;            // 0..3 -> freq groups f = m, m+4, ...
    float v[64];
    if (axisH) {
        int cc = flip ? (63 - col) : col;
#pragma unroll
        for (int n = 0; n < 64; n++) v[n] = slab[n * 65 + cc];
    } else {
#pragma unroll
        for (int n = 0; n < 64; n++) v[n] = slab[col * 65 + n];
    }

    int i = b >> 6, c = b & 63;
    for (int f = m; f < NF; f += 4) {
        float ar = 0.f, ai = 0.f;
        const float2* twf = &stw[f * 64];
#pragma unroll
        for (int n = 0; n < 64; n++) {
            float2 t = twf[n];
            ar = fmaf(v[n],  t.x, ar);
            ai = fmaf(v[n], -t.y, ai);
        }
        dst[((size_t)f * BS + i) * KDIM + c * 64 + col] = make_float2(ar, ai);
    }
}

// -------- per-frequency complex GEMM: C[f][i][j] = sum_k S[f][i][k]*conj(G[f][j][k]) --------
// grid = 33 freqs * 4 k-chunks = 132 blocks (single balanced wave), 256 threads,
// each thread a 2x2 (i,j) complex tile, K = 1024 per block.
__global__ void k_fgemm(int sel) {
    __shared__ float2 sS[64 * 33];
    __shared__ float2 sG[64 * 33];
    const float2* S = sel ? g_Sw : g_Sh;
    const float2* G = sel ? g_Gw : g_Gh;
    float2* Cp      = sel ? g_CpW : g_CpH;

    int f  = blockIdx.x >> 2;
    int kc = blockIdx.x & 3;
    int tid = threadIdx.x;
    int li = tid >> 3;
    int ls = tid & 7;
    int i0 = (tid >> 4) * 2;
    int j0 = (tid & 15) * 2;

    float c00r = 0, c00i = 0, c01r = 0, c01i = 0;
    float c10r = 0, c10i = 0, c11r = 0, c11i = 0;

    const float2* Sb = S + (size_t)f * BS * KDIM + kc * 1024;
    const float2* Gb = G + (size_t)f * BS * KDIM + kc * 1024;

    for (int kt = 0; kt < 16; kt++) {
        __syncthreads();
#pragma unroll
        for (int u = 0; u < 8; u++) {
            int k = ls + u * 8;
            sS[k * 33 + li] = Sb[(size_t)li * KDIM + kt * 64 + k];
            sG[k * 33 + li] = Gb[(size_t)li * KDIM + kt * 64 + k];
        }
        __syncthreads();
#pragma unroll 8
        for (int k = 0; k < 64; k++) {
            float2 a0 = sS[k * 33 + i0];
            float2 a1 = sS[k * 33 + i0 + 1];
            float2 b0 = sG[k * 33 + j0];
            float2 b1 = sG[k * 33 + j0 + 1];
            c00r += a0.x * b0.x + a0.y * b0.y;  c00i += a0.y * b0.x - a0.x * b0.y;
            c01r += a0.x * b1.x + a0.y * b1.y;  c01i += a0.y * b1.x - a0.x * b1.y;
            c10r += a1.x * b0.x + a1.y * b0.y;  c10i += a1.y * b0.x - a1.x * b0.y;
            c11r += a1.x * b1.x + a1.y * b1.y;  c11i += a1.y * b1.x - a1.x * b1.y;
        }
    }
    float2* outp = Cp + ((size_t)kc * NF + f) * BS * BS;
    outp[i0 * 32 + j0]           = make_float2(c00r, c00i);
    outp[i0 * 32 + j0 + 1]       = make_float2(c01r, c01i);
    outp[(i0 + 1) * 32 + j0]     = make_float2(c10r, c10i);
    outp[(i0 + 1) * 32 + j0 + 1] = make_float2(c11r, c11i);
}

// -------- per-sat L2 norm (norm of cropped == norm of full sat: circular crop) --------
__global__ void k_norm(const float* __restrict__ sat) {
    __shared__ float red[256];
    int i = blockIdx.x;
    const float* p = sat + (size_t)i * 262144;
    float s = 0.f;
    for (int t = threadIdx.x; t < 262144; t += 256) { float v = p[t]; s = fmaf(v, v, s); }
    red[threadIdx.x] = s;
    __syncthreads();
    for (int o = 128; o > 0; o >>= 1) {
        if (threadIdx.x < o) red[threadIdx.x] += red[threadIdx.x + o];
        __syncthreads();
    }
    if (threadIdx.x == 0) g_norm[i] = sqrtf(red[0] + 1e-8f);
}

// -------- fused inverse transform + first-max argmax + distance --------
// grid = 1024 blocks (i*32+j), 64 threads (one per shift)
__global__ void k_inv(float* __restrict__ out_dist, float* __restrict__ out_orien_f) {
    __shared__ float2 CH[NF], CW[NF];
    __shared__ float valsH[64], valsW[64];
    int i = blockIdx.x >> 5, j = blockIdx.x & 31;
    int s = threadIdx.x;

    if (s < NF) {
        float xr = 0, xi = 0, yr = 0, yi = 0;
#pragma unroll
        for (int kc = 0; kc < NKC; kc++) {
            float2 a = g_CpH[((kc * NF + s) * BS + i) * BS + j];
            float2 b = g_CpW[((kc * NF + s) * BS + i) * BS + j];
            xr += a.x; xi += a.y; yr += b.x; yi += b.y;
        }
        CH[s] = make_float2(xr, xi);
        CW[s] = make_float2(yr, yi);
    }
    __syncthreads();

    float sgn = (s & 1) ? -1.f : 1.f;
    float accH = CH[0].x + sgn * CH[32].x;
    float accW = CW[0].x + sgn * CW[32].x;
#pragma unroll
    for (int f = 1; f < 32; f++) {
        float2 t = g_tw[f * 64 + s];
        accH += 2.f * (CH[f].x * t.x - CH[f].y * t.y);
        accW += 2.f * (CW[f].x * t.x - CW[f].y * t.y);
    }
    valsH[s] = accH;
    valsW[s] = accW;
    __syncthreads();

    if (s == 0) {
        float best = valsH[0]; int bi = 0;
        for (int t = 1; t < 64; t++)
            if (valsH[t] > best) { best = valsH[t]; bi = t; }   // first max
        out_orien_f[i * 32 + j] = (float)bi;
        float q = valsW[bi] * (1.f / 64.f);
        float dot = q / g_norm[i];
        out_dist[j * 32 + i] = 2.f - 2.f * dot;
    }
}

extern "C" void kernel_launch(void* const* d_in, const int* in_sizes, int n_in,
                              void* d_out, int out_size) {
    (void)in_sizes; (void)n_in; (void)out_size;
    const float* sat = (const float*)d_in[0];
    const float* grd = (const float*)d_in[1];
    float* out = (float*)d_out;

    cudaMemcpyAsync(out, sat, (size_t)SATN * sizeof(float), cudaMemcpyDeviceToDevice);
    cudaMemcpyAsync(out + SATN, grd, (size_t)SATN * sizeof(float), cudaMemcpyDeviceToDevice);

    k_init<<<9, 256>>>();

    // R1-verbatim DFTs (proven correct)
    k_dft<<<2048, 256>>>(sat, 0, 1, 0);   // g_Sh
    k_dft<<<2048, 256>>>(grd, 1, 1, 1);   // g_Gh (w-flipped)
    k_dft<<<2048, 256>>>(sat, 2, 0, 0);   // g_Sw
    k_dft<<<2048, 256>>>(grd, 3, 0, 0);   // g_Gw

    k_fgemm<<<NF * NKC, 256>>>(0);        // corr (h-axis)
    k_fgemm<<<NF * NKC, 256>>>(1);        // dot  (w-axis)

    k_norm<<<32, 256>>>(sat);

    float* out_dist  = out + (size_t)2 * SATN;
    float* out_orien = out + (size_t)2 * SATN + 1024;
    k_inv<<<1024, 64>>>(out_dist, out_orien);
}

// round 4
// speedup vs baseline: 1.3096x; 1.1358x over previous
#include <cuda_runtime.h>
#include <math.h>

#define BS 32
#define NF 33
#define KDIM 4096
#define SATN (32*64*64*64)
#define NKC 8            // k-chunks per freq in fgemm

// -------- device scratch --------
__device__ float2 g_Sh[(size_t)NF * BS * KDIM];
__device__ float2 g_Gh[(size_t)NF * BS * KDIM];
__device__ float2 g_Sw[(size_t)NF * BS * KDIM];
__device__ float2 g_Gw[(size_t)NF * BS * KDIM];
__device__ float2 g_CpH[NKC * NF * BS * BS];
__device__ float2 g_CpW[NKC * NF * BS * BS];
__device__ float2 g_tw[NF * 64];
__device__ float  g_norm[BS];

// -------- twiddle init: g_tw[f*64+n] = (cos,sin)(2*pi*f*n/64) --------
__global__ void k_init() {
    int idx = blockIdx.x * blockDim.x + threadIdx.x;
    if (idx < NF * 64) {
        int f = idx >> 6, n = idx & 63;
        float x = (float)((f * n) & 63) / 32.0f;
        float s, c;
        sincospif(x, &s, &c);
        g_tw[idx] = make_float2(c, s);
    }
}

// -------- DFT along one axis of each [64h x 64w] slab --------
// Identical math/order to the proven R1 kernel; only the twiddle loads are
// vectorized (float4 = two complex twiddles per LDS.128).
__global__ void k_dft(const float* __restrict__ src, int sel, int axisH, int flip) {
    __shared__ float  slab[64 * 65];
    __shared__ __align__(16) float2 stw[NF * 64];
    float2* dst = (sel == 0) ? g_Sh : (sel == 1) ? g_Gh : (sel == 2) ? g_Sw : g_Gw;

    int b = blockIdx.x;            // i*64 + c
    int tid = threadIdx.x;
    const float* p = src + (size_t)b * 4096;

#pragma unroll
    for (int t = 0; t < 16; t++) {
        int idx = tid + t * 256;
        slab[(idx >> 6) * 65 + (idx & 63)] = p[idx];
    }
    for (int t = tid; t < NF * 64; t += 256) stw[t] = g_tw[t];
    __syncthreads();

    int col = tid & 63;
    int m   = tid >> 6;            // 0..3 -> freq groups f = m, m+4, ...
    float v[64];
    if (axisH) {
        int cc = flip ? (63 - col) : col;
#pragma unroll
        for (int n = 0; n < 64; n++) v[n] = slab[n * 65 + cc];
    } else {
#pragma unroll
        for (int n = 0; n < 64; n++) v[n] = slab[col * 65 + n];
    }

    int i = b >> 6, c = b & 63;
    for (int f = m; f < NF; f += 4) {
        float ar = 0.f, ai = 0.f;
        const float4* twf4 = (const float4*)(stw + f * 64);
#pragma unroll
        for (int n2 = 0; n2 < 32; n2++) {
            float4 t = twf4[n2];            // (cos[2n2], sin[2n2], cos[2n2+1], sin[2n2+1])
            ar = fmaf(v[2 * n2],     t.x, ar);
            ai = fmaf(v[2 * n2],    -t.y, ai);
            ar = fmaf(v[2 * n2 + 1], t.z, ar);
            ai = fmaf(v[2 * n2 + 1],-t.w, ai);
        }
        dst[((size_t)f * BS + i) * KDIM + c * 64 + col] = make_float2(ar, ai);
    }
}

// -------- per-frequency complex GEMM: C[f][i][j] = sum_k S[f][i][k]*conj(G[f][j][k]) --------
// grid = 2 * 33 * 8 = 528 blocks, 256 threads, 2 blocks/SM.
// smem layout [k][i] with pad 34 (float2): a-load is float4 over (i0,i0+1) (broadcast),
// b-load float4 over (j0,j0+1) (16 contiguous float4 per warp -> conflict-free).
__global__ void __launch_bounds__(256, 2) k_fgemm2() {
    __shared__ __align__(16) float2 sS[64 * 34];
    __shared__ __align__(16) float2 sG[64 * 34];

    int bid = blockIdx.x;
    int sel = (bid >= NF * NKC);
    if (sel) bid -= NF * NKC;
    int f  = bid >> 3;
    int kc = bid & 7;

    const float2* S = sel ? g_Sw : g_Sh;
    const float2* G = sel ? g_Gw : g_Gh;
    float2* Cp      = sel ? g_CpW : g_CpH;

    int tid = threadIdx.x;
    int i0 = (tid >> 4) * 2;       // 0..30 even
    int j0 = (tid & 15) * 2;       // 0..30 even
    int li = tid >> 3;             // staging row 0..31
    int ls = tid & 7;              // staging float4 k-index base

    const float2* Sb = S + (size_t)f * BS * KDIM + kc * 512;
    const float2* Gb = G + (size_t)f * BS * KDIM + kc * 512;
    const float4* Sg4 = (const float4*)(Sb + (size_t)li * KDIM);
    const float4* Gg4 = (const float4*)(Gb + (size_t)li * KDIM);

    float c00r = 0, c00i = 0, c01r = 0, c01i = 0;
    float c10r = 0, c10i = 0, c11r = 0, c11i = 0;

    const float4* sS4 = (const float4*)sS;
    const float4* sG4 = (const float4*)sG;
    int ia = i0 >> 1;              // float4 column index for a
    int jb = j0 >> 1;              // float4 column index for b

    for (int kt = 0; kt < 8; kt++) {
        __syncthreads();
#pragma unroll
        for (int u = 0; u < 4; u++) {
            int k4 = ls + u * 8;                     // covers k = 2*k4, 2*k4+1
            float4 s = Sg4[kt * 32 + k4];
            float4 g = Gg4[kt * 32 + k4];
            sS[(2 * k4)     * 34 + li] = make_float2(s.x, s.y);
            sS[(2 * k4 + 1) * 34 + li] = make_float2(s.z, s.w);
            sG[(2 * k4)     * 34 + li] = make_float2(g.x, g.y);
            sG[(2 * k4 + 1) * 34 + li] = make_float2(g.z, g.w);
        }
        __syncthreads();
#pragma unroll 16
        for (int k = 0; k < 64; k++) {
            float4 a = sS4[k * 17 + ia];    // (S[i0].re, S[i0].im, S[i0+1].re, S[i0+1].im)
            float4 b = sG4[k * 17 + jb];
            c00r += a.x * b.x + a.y * b.y;  c00i += a.y * b.x - a.x * b.y;
            c01r += a.x * b.z + a.y * b.w;  c01i += a.y * b.z - a.x * b.w;
            c10r += a.z * b.x + a.w * b.y;  c10i += a.w * b.x - a.z * b.y;
            c11r += a.z * b.z + a.w * b.w;  c11i += a.w * b.z - a.z * b.w;
        }
    }
    float2* outp = Cp + ((size_t)kc * NF + f) * BS * BS;
    outp[i0 * 32 + j0]           = make_float2(c00r, c00i);
    outp[i0 * 32 + j0 + 1]       = make_float2(c01r, c01i);
    outp[(i0 + 1) * 32 + j0]     = make_float2(c10r, c10i);
    outp[(i0 + 1) * 32 + j0 + 1] = make_float2(c11r, c11i);
}

// -------- per-sat L2 norm (norm of cropped == norm of full sat: circular crop) --------
__global__ void k_norm(const float* __restrict__ sat) {
    __shared__ float red[256];
    int i = blockIdx.x;
    const float* p = sat + (size_t)i * 262144;
    float s = 0.f;
    for (int t = threadIdx.x; t < 262144; t += 256) { float v = p[t]; s = fmaf(v, v, s); }
    red[threadIdx.x] = s;
    __syncthreads();
    for (int o = 128; o > 0; o >>= 1) {
        if (threadIdx.x < o) red[threadIdx.x] += red[threadIdx.x + o];
        __syncthreads();
    }
    if (threadIdx.x == 0) g_norm[i] = sqrtf(red[0] + 1e-8f);
}

// -------- fused inverse transform + first-max argmax + distance --------
// grid = 1024 blocks (i*32+j), 64 threads (one per shift)
__global__ void k_inv(float* __restrict__ out_dist, float* __restrict__ out_orien_f) {
    __shared__ float2 CH[NF], CW[NF];
    __shared__ float valsH[64], valsW[64];
    int i = blockIdx.x >> 5, j = blockIdx.x & 31;
    int s = threadIdx.x;

    if (s < NF) {
        float xr = 0, xi = 0, yr = 0, yi = 0;
#pragma unroll
        for (int kc = 0; kc < NKC; kc++) {
            float2 a = g_CpH[((kc * NF + s) * BS + i) * BS + j];
            float2 b = g_CpW[((kc * NF + s) * BS + i) * BS + j];
            xr += a.x; xi += a.y; yr += b.x; yi += b.y;
        }
        CH[s] = make_float2(xr, xi);
        CW[s] = make_float2(yr, yi);
    }
    __syncthreads();

    float sgn = (s & 1) ? -1.f : 1.f;
    float accH = CH[0].x + sgn * CH[32].x;
    float accW = CW[0].x + sgn * CW[32].x;
#pragma unroll
    for (int f = 1; f < 32; f++) {
        float2 t = g_tw[f * 64 + s];
        accH += 2.f * (CH[f].x * t.x - CH[f].y * t.y);
        accW += 2.f * (CW[f].x * t.x - CW[f].y * t.y);
    }
    valsH[s] = accH;
    valsW[s] = accW;
    __syncthreads();

    if (s == 0) {
        float best = valsH[0]; int bi = 0;
        for (int t = 1; t < 64; t++)
            if (valsH[t] > best) { best = valsH[t]; bi = t; }   // first max
        out_orien_f[i * 32 + j] = (float)bi;
        float q = valsW[bi] * (1.f / 64.f);
        float dot = q / g_norm[i];
        out_dist[j * 32 + i] = 2.f - 2.f * dot;
    }
}

extern "C" void kernel_launch(void* const* d_in, const int* in_sizes, int n_in,
                              void* d_out, int out_size) {
    (void)in_sizes; (void)n_in; (void)out_size;
    const float* sat = (const float*)d_in[0];
    const float* grd = (const float*)d_in[1];
    float* out = (float*)d_out;

    cudaMemcpyAsync(out, sat, (size_t)SATN * sizeof(float), cudaMemcpyDeviceToDevice);
    cudaMemcpyAsync(out + SATN, grd, (size_t)SATN * sizeof(float), cudaMemcpyDeviceToDevice);

    k_init<<<9, 256>>>();

    k_dft<<<2048, 256>>>(sat, 0, 1, 0);   // g_Sh
    k_dft<<<2048, 256>>>(grd, 1, 1, 1);   // g_Gh (w-flipped)
    k_dft<<<2048, 256>>>(sat, 2, 0, 0);   // g_Sw
    k_dft<<<2048, 256>>>(grd, 3, 0, 0);   // g_Gw

    k_fgemm2<<<2 * NF * NKC, 256>>>();    // corr + dot, single launch

    k_norm<<<32, 256>>>(sat);

    float* out_dist  = out + (size_t)2 * SATN;
    float* out_orien = out + (size_t)2 * SATN + 1024;
    k_inv<<<1024, 64>>>(out_dist, out_orien);
}

// round 5
// speedup vs baseline: 2.0236x; 1.5451x over previous
#include <cuda_runtime.h>
#include <math.h>

#define BS 32
#define NF 33
#define KDIM 4096
#define SATN (32*64*64*64)
#define NKC 8            // k-chunks per freq in fgemm

// -------- device scratch --------
__device__ float2 g_Sh[(size_t)NF * BS * KDIM];
__device__ float2 g_Gh[(size_t)NF * BS * KDIM];
__device__ float2 g_Sw[(size_t)NF * BS * KDIM];
__device__ float2 g_Gw[(size_t)NF * BS * KDIM];
__device__ float2 g_CpH[NKC * NF * BS * BS];
__device__ float2 g_CpW[NKC * NF * BS * BS];
__device__ float2 g_tw[NF * 64];
__device__ float  g_normp[2048];   // per-(i,c) slab sum-of-squares partials
__device__ float  g_norm[BS];

// -------- twiddle init: g_tw[f*64+n] = (cos,sin)(2*pi*f*n/64) --------
__global__ void k_init() {
    int idx = blockIdx.x * blockDim.x + threadIdx.x;
    if (idx < NF * 64) {
        int f = idx >> 6, n = idx & 63;
        float x = (float)((f * n) & 63) / 32.0f;
        float s, c;
        sincospif(x, &s, &c);
        g_tw[idx] = make_float2(c, s);
    }
}

// -------- DFT along one axis of each [64h x 64w] slab, real-input symmetry --------
// grid = 2048 blocks (i*64 + c), 256 threads.
// ar(f) = e0 + e32*cos(pi f) + sum_{n=1..31} e[n] cos(2pi f n/64)
// ai_out(f) = -sum_{n=1..31} o[n] sin(2pi f n/64)
// where e[n] = v[n]+v[64-n], o[n] = v[n]-v[64-n]. Identical value to the proven
// full DFT (cos even / sin odd about n=32; sin(0)=sin(pi f)=0 exact in table).
__global__ void __launch_bounds__(256, 2)
k_dft(const float* __restrict__ src, int sel, int axisH, int flip, int do_norm) {
    __shared__ float  slab[64 * 65];
    __shared__ __align__(16) float2 stw[NF * 64];
    __shared__ float red[8];
    float2* dst = (sel == 0) ? g_Sh : (sel == 1) ? g_Gh : (sel == 2) ? g_Sw : g_Gw;

    int b = blockIdx.x;            // i*64 + c
    int tid = threadIdx.x;
    const float* p = src + (size_t)b * 4096;

    float nacc = 0.f;
#pragma unroll
    for (int t = 0; t < 16; t++) {
        int idx = tid + t * 256;
        float v = p[idx];
        slab[(idx >> 6) * 65 + (idx & 63)] = v;
        nacc = fmaf(v, v, nacc);
    }
    for (int t = tid; t < NF * 64; t += 256) stw[t] = g_tw[t];

    if (do_norm) {
        // deterministic per-block sum of squares -> g_normp[b]
#pragma unroll
        for (int o = 16; o > 0; o >>= 1)
            nacc += __shfl_down_sync(0xffffffffu, nacc, o);
        if ((tid & 31) == 0) red[tid >> 5] = nacc;
    }
    __syncthreads();
    if (do_norm && tid == 0) {
        float s = 0.f;
#pragma unroll
        for (int w = 0; w < 8; w++) s += red[w];
        g_normp[b] = s;
    }

    int col = tid & 63;
    int m   = tid >> 6;            // 0..3

    float e[33], o[31];
    if (axisH) {
        int cc = flip ? (63 - col) : col;
        e[0]  = slab[cc];
        e[32] = slab[32 * 65 + cc];
#pragma unroll
        for (int n = 1; n < 32; n++) {
            float a = slab[n * 65 + cc];
            float bb = slab[(64 - n) * 65 + cc];
            e[n] = a + bb;
            o[n - 1] = a - bb;
        }
    } else {
        const float* row = slab + col * 65;
        e[0]  = row[0];
        e[32] = row[32];
#pragma unroll
        for (int n = 1; n < 32; n++) {
            float a = row[n], bb = row[64 - n];
            e[n] = a + bb;
            o[n - 1] = a - bb;
        }
    }

    int i = b >> 6, c = b & 63;
    size_t off = (size_t)c * 64 + col;

    // freq pairs (f1, f1+16): m=0..3, u=0..3 covers f = 0..31; f=32 handled by m==0.
#pragma unroll
    for (int u = 0; u < 4; u++) {
        int f1 = m + 4 * u;
        int f2 = f1 + 16;
        const float2* t1 = stw + f1 * 64;
        const float2* t2 = stw + f2 * 64;
        float ar1 = fmaf(e[32], t1[32].x, e[0]);
        float ar2 = fmaf(e[32], t2[32].x, e[0]);
        float ai1 = 0.f, ai2 = 0.f;
#pragma unroll
        for (int n = 1; n < 32; n++) {
            float2 w1 = t1[n];
            float2 w2 = t2[n];
            ar1 = fmaf(e[n], w1.x, ar1);
            ai1 = fmaf(o[n - 1], w1.y, ai1);
            ar2 = fmaf(e[n], w2.x, ar2);
            ai2 = fmaf(o[n - 1], w2.y, ai2);
        }
        dst[((size_t)f1 * BS + i) * KDIM + off] = make_float2(ar1, -ai1);
        dst[((size_t)f2 * BS + i) * KDIM + off] = make_float2(ar2, -ai2);
    }
    if (m == 0) {   // whole warps 0-1, no intra-warp divergence
        const float2* t1 = stw + 32 * 64;
        float ar = fmaf(e[32], t1[32].x, e[0]);
        float ai = 0.f;
#pragma unroll
        for (int n = 1; n < 32; n++) {
            float2 w1 = t1[n];
            ar = fmaf(e[n], w1.x, ar);
            ai = fmaf(o[n - 1], w1.y, ai);
        }
        dst[((size_t)32 * BS + i) * KDIM + off] = make_float2(ar, -ai);
    }
}

// -------- reduce norm partials: g_norm[i] = sqrt(sum_c g_normp[i*64+c] + 1e-8) --------
__global__ void k_nred() {
    __shared__ float red[2];
    int i = blockIdx.x, t = threadIdx.x;   // 32 blocks, 64 threads
    float v = g_normp[i * 64 + t];
#pragma unroll
    for (int o = 16; o > 0; o >>= 1) v += __shfl_down_sync(0xffffffffu, v, o);
    if ((t & 31) == 0) red[t >> 5] = v;
    __syncthreads();
    if (t == 0) g_norm[i] = sqrtf(red[0] + red[1] + 1e-8f);
}

// -------- per-frequency complex GEMM: C[f][i][j] = sum_k S[f][i][k]*conj(G[f][j][k]) --------
__global__ void __launch_bounds__(256, 2) k_fgemm2() {
    __shared__ __align__(16) float2 sS[64 * 34];
    __shared__ __align__(16) float2 sG[64 * 34];

    int bid = blockIdx.x;
    int sel = (bid >= NF * NKC);
    if (sel) bid -= NF * NKC;
    int f  = bid >> 3;
    int kc = bid & 7;

    const float2* S = sel ? g_Sw : g_Sh;
    const float2* G = sel ? g_Gw : g_Gh;
    float2* Cp      = sel ? g_CpW : g_CpH;

    int tid = threadIdx.x;
    int i0 = (tid >> 4) * 2;
    int j0 = (tid & 15) * 2;
    int li = tid >> 3;
    int ls = tid & 7;

    const float2* Sb = S + (size_t)f * BS * KDIM + kc * 512;
    const float2* Gb = G + (size_t)f * BS * KDIM + kc * 512;
    const float4* Sg4 = (const float4*)(Sb + (size_t)li * KDIM);
    const float4* Gg4 = (const float4*)(Gb + (size_t)li * KDIM);

    float c00r = 0, c00i = 0, c01r = 0, c01i = 0;
    float c10r = 0, c10i = 0, c11r = 0, c11i = 0;

    const float4* sS4 = (const float4*)sS;
    const float4* sG4 = (const float4*)sG;
    int ia = i0 >> 1;
    int jb = j0 >> 1;

    for (int kt = 0; kt < 8; kt++) {
        __syncthreads();
#pragma unroll
        for (int u = 0; u < 4; u++) {
            int k4 = ls + u * 8;
            float4 s = Sg4[kt * 32 + k4];
            float4 g = Gg4[kt * 32 + k4];
            sS[(2 * k4)     * 34 + li] = make_float2(s.x, s.y);
            sS[(2 * k4 + 1) * 34 + li] = make_float2(s.z, s.w);
            sG[(2 * k4)     * 34 + li] = make_float2(g.x, g.y);
            sG[(2 * k4 + 1) * 34 + li] = make_float2(g.z, g.w);
        }
        __syncthreads();
#pragma unroll 16
        for (int k = 0; k < 64; k++) {
            float4 a = sS4[k * 17 + ia];
            float4 b = sG4[k * 17 + jb];
            c00r += a.x * b.x + a.y * b.y;  c00i += a.y * b.x - a.x * b.y;
            c01r += a.x * b.z + a.y * b.w;  c01i += a.y * b.z - a.x * b.w;
            c10r += a.z * b.x + a.w * b.y;  c10i += a.w * b.x - a.z * b.y;
            c11r += a.z * b.z + a.w * b.w;  c11i += a.w * b.z - a.z * b.w;
        }
    }
    float2* outp = Cp + ((size_t)kc * NF + f) * BS * BS;
    outp[i0 * 32 + j0]           = make_float2(c00r, c00i);
    outp[i0 * 32 + j0 + 1]       = make_float2(c01r, c01i);
    outp[(i0 + 1) * 32 + j0]     = make_float2(c10r, c10i);
    outp[(i0 + 1) * 32 + j0 + 1] = make_float2(c11r, c11i);
}

// -------- fused inverse transform + first-max argmax + distance --------
__global__ void k_inv(float* __restrict__ out_dist, float* __restrict__ out_orien_f) {
    __shared__ float2 CH[NF], CW[NF];
    __shared__ float valsH[64], valsW[64];
    int i = blockIdx.x >> 5, j = blockIdx.x & 31;
    int s = threadIdx.x;

    if (s < NF) {
        float xr = 0, xi = 0, yr = 0, yi = 0;
#pragma unroll
        for (int kc = 0; kc < NKC; kc++) {
            float2 a = g_CpH[((kc * NF + s) * BS + i) * BS + j];
            float2 b = g_CpW[((kc * NF + s) * BS + i) * BS + j];
            xr += a.x; xi += a.y; yr += b.x; yi += b.y;
        }
        CH[s] = make_float2(xr, xi);
        CW[s] = make_float2(yr, yi);
    }
    __syncthreads();

    float sgn = (s & 1) ? -1.f : 1.f;
    float accH = CH[0].x + sgn * CH[32].x;
    float accW = CW[0].x + sgn * CW[32].x;
#pragma unroll
    for (int f = 1; f < 32; f++) {
        float2 t = g_tw[f * 64 + s];
        accH += 2.f * (CH[f].x * t.x - CH[f].y * t.y);
        accW += 2.f * (CW[f].x * t.x - CW[f].y * t.y);
    }
    valsH[s] = accH;
    valsW[s] = accW;
    __syncthreads();

    if (s == 0) {
        float best = valsH[0]; int bi = 0;
        for (int t = 1; t < 64; t++)
            if (valsH[t] > best) { best = valsH[t]; bi = t; }   // first max
        out_orien_f[i * 32 + j] = (float)bi;
        float q = valsW[bi] * (1.f / 64.f);
        float dot = q / g_norm[i];
        out_dist[j * 32 + i] = 2.f - 2.f * dot;
    }
}

extern "C" void kernel_launch(void* const* d_in, const int* in_sizes, int n_in,
                              void* d_out, int out_size) {
    (void)in_sizes; (void)n_in; (void)out_size;
    const float* sat = (const float*)d_in[0];
    const float* grd = (const float*)d_in[1];
    float* out = (float*)d_out;

    cudaMemcpyAsync(out, sat, (size_t)SATN * sizeof(float), cudaMemcpyDeviceToDevice);
    cudaMemcpyAsync(out + SATN, grd, (size_t)SATN * sizeof(float), cudaMemcpyDeviceToDevice);

    k_init<<<9, 256>>>();

    k_dft<<<2048, 256>>>(sat, 0, 1, 0, 1);   // g_Sh + norm partials
    k_dft<<<2048, 256>>>(grd, 1, 1, 1, 0);   // g_Gh (w-flipped)
    k_dft<<<2048, 256>>>(sat, 2, 0, 0, 0);   // g_Sw
    k_dft<<<2048, 256>>>(grd, 3, 0, 0, 0);   // g_Gw

    k_nred<<<32, 64>>>();

    k_fgemm2<<<2 * NF * NKC, 256>>>();       // corr + dot, single launch

    float* out_dist  = out + (size_t)2 * SATN;
    float* out_orien = out + (size_t)2 * SATN + 1024;
    k_inv<<<1024, 64>>>(out_dist, out_orien);
}

// round 6
// speedup vs baseline: 2.3178x; 1.1454x over previous
#include <cuda_runtime.h>
#include <math.h>

#define BS 32
#define NF 33
#define KDIM 4096
#define SATN (32*64*64*64)
#define NKC 8            // k-chunks per freq in fgemm

// -------- device scratch --------
__device__ float2 g_Sh[(size_t)NF * BS * KDIM];
__device__ float2 g_Gh[(size_t)NF * BS * KDIM];
__device__ float2 g_Sw[(size_t)NF * BS * KDIM];
__device__ float2 g_Gw[(size_t)NF * BS * KDIM];
__device__ float2 g_CpH[NKC * NF * BS * BS];
__device__ float2 g_CpW[NKC * NF * BS * BS];
__device__ float2 g_tw[NF * 64];
__device__ float  g_normp[2048];
__device__ float  g_norm[BS];

// -------- twiddle init: g_tw[f*64+n] = (cos,sin)(2*pi*f*n/64) --------
__global__ void k_init() {
    int idx = blockIdx.x * blockDim.x + threadIdx.x;
    if (idx < NF * 64) {
        int f = idx >> 6, n = idx & 63;
        float x = (float)((f * n) & 63) / 32.0f;
        float s, c;
        sincospif(x, &s, &c);
        g_tw[idx] = make_float2(c, s);
    }
}

// Build e/o folded arrays in smem for one axis.
// se[n][col] = v[n]+v[64-n], so[n][col] = v[n]-v[64-n] (n=1..31), se[0]=v0, se[32]=v32.
// cc = source column (axisH, flip already applied) or source row (axisW).
__device__ __forceinline__ void dft_build(
    const float* slab, float* se, float* so, int axisH, int cc, int col, int m)
{
#pragma unroll
    for (int nn = 0; nn < 8; nn++) {
        int n = m + 4 * nn;                    // covers 0..31 across m=0..3
        float a, bb;
        if (axisH) {
            a  = slab[n * 65 + cc];
            bb = n ? slab[(64 - n) * 65 + cc] : 0.f;
        } else {
            a  = slab[cc * 65 + n];
            bb = n ? slab[cc * 65 + (64 - n)] : 0.f;
        }
        se[n * 65 + col] = a + bb;
        so[n * 65 + col] = a - bb;
    }
    if (m == 0)
        se[32 * 65 + col] = axisH ? slab[32 * 65 + cc] : slab[cc * 65 + 32];
}

// Compute rfft bins from se/so. Thread (col, m) does freq pairs (f1, f1+16),
// f1 = m+4u; twiddle for f1+16 derived by exact (-i)^n rotation of f1's twiddle.
// f=32 (m==0) is the exact parity sum. Same values as the R5-proven kernel.
__device__ __forceinline__ void dft_compute(
    const float* se, const float* so, const float2* stw,
    float2* __restrict__ dst, int i, size_t off, int col, int m)
{
    float e0  = se[col];
    float e32 = se[32 * 65 + col];
    float sgn = (m & 1) ? -1.f : 1.f;          // (-1)^f1, parity of f1 = parity of m
    float base = fmaf(sgn, e32, e0);

#pragma unroll
    for (int u = 0; u < 4; u++) {
        int f1 = m + 4 * u;                    // 0..15
        const float2* t1 = stw + f1 * 64;
        float ar1 = base, ar2 = base, ai1 = 0.f, ai2 = 0.f;
#pragma unroll
        for (int n = 1; n < 32; n++) {
            float en = se[n * 65 + col];
            float on = so[n * 65 + col];
            float2 w = t1[n];
            ar1 = fmaf(en, w.x, ar1);
            ai1 = fmaf(on, w.y, ai1);
            float c2, s2;                      // twiddle(f1+16, n) = twiddle(f1,n) rotated
            if ((n & 3) == 0)      { c2 =  w.x; s2 =  w.y; }
            else if ((n & 3) == 1) { c2 = -w.y; s2 =  w.x; }
            else if ((n & 3) == 2) { c2 = -w.x; s2 = -w.y; }
            else                   { c2 =  w.y; s2 = -w.x; }
            ar2 = fmaf(en, c2, ar2);
            ai2 = fmaf(on, s2, ai2);
        }
        dst[((size_t)f1 * BS + i) * KDIM + off]        = make_float2(ar1, -ai1);
        dst[((size_t)(f1 + 16) * BS + i) * KDIM + off] = make_float2(ar2, -ai2);
    }
    if (m == 0) {                              // f = 32: cos = (-1)^n, sin = 0
        float ar = e0 + e32;
        float sg = -1.f;
#pragma unroll
        for (int n = 1; n < 32; n++) {
            ar = fmaf(se[n * 65 + col], sg, ar);
            sg = -sg;
        }
        dst[((size_t)32 * BS + i) * KDIM + off] = make_float2(ar, 0.f);
    }
}

// -------- merged DFT: sat+grd, H+W axes, passthrough copy, norm partials --------
// grid = 4096 (b<2048: sat, else grd), 256 threads.
__global__ void __launch_bounds__(256, 4)
k_dft3(const float* __restrict__ sat, const float* __restrict__ grd,
       float* __restrict__ out)
{
    __shared__ float slab[64 * 65];
    __shared__ __align__(16) float2 stw[16 * 64];
    __shared__ float se[33 * 65];
    __shared__ float so[32 * 65];
    __shared__ float red[8];

    int b = blockIdx.x;
    int tid = threadIdx.x;
    int is_grd = (b >= 2048);
    int b2 = is_grd ? (b - 2048) : b;
    const float* p = (is_grd ? grd : sat) + (size_t)b2 * 4096;
    float* op = out + (is_grd ? (size_t)SATN : 0) + (size_t)b2 * 4096;

    float nacc = 0.f;
#pragma unroll
    for (int t = 0; t < 16; t++) {
        int idx = tid + t * 256;
        float v = p[idx];
        slab[(idx >> 6) * 65 + (idx & 63)] = v;
        op[idx] = v;                            // passthrough output
        nacc = fmaf(v, v, nacc);
    }
    for (int t = tid; t < 16 * 64; t += 256) stw[t] = g_tw[t];

    if (!is_grd) {
#pragma unroll
        for (int o = 16; o > 0; o >>= 1)
            nacc += __shfl_down_sync(0xffffffffu, nacc, o);
        if ((tid & 31) == 0) red[tid >> 5] = nacc;
    }
    __syncthreads();
    if (!is_grd && tid == 0) {
        float s = 0.f;
#pragma unroll
        for (int w = 0; w < 8; w++) s += red[w];
        g_normp[b2] = s;
    }

    int col = tid & 63;
    int m   = tid >> 6;
    int i = b2 >> 6, c = b2 & 63;
    size_t off = (size_t)c * 64 + col;

    // ---- phase H (grd is w-flipped on this axis) ----
    {
        int cc = is_grd ? (63 - col) : col;
        dft_build(slab, se, so, 1, cc, col, m);
        __syncthreads();
        dft_compute(se, so, stw, is_grd ? g_Gh : g_Sh, i, off, col, m);
    }
    __syncthreads();
    // ---- phase W ----
    {
        dft_build(slab, se, so, 0, col, col, m);
        __syncthreads();
        dft_compute(se, so, stw, is_grd ? g_Gw : g_Sw, i, off, col, m);
    }
}

// -------- reduce norm partials --------
__global__ void k_nred() {
    __shared__ float red[2];
    int i = blockIdx.x, t = threadIdx.x;   // 32 blocks, 64 threads
    float v = g_normp[i * 64 + t];
#pragma unroll
    for (int o = 16; o > 0; o >>= 1) v += __shfl_down_sync(0xffffffffu, v, o);
    if ((t & 31) == 0) red[t >> 5] = v;
    __syncthreads();
    if (t == 0) g_norm[i] = sqrtf(red[0] + red[1] + 1e-8f);
}

// -------- per-frequency complex GEMM: C[f][i][j] = sum_k S[f][i][k]*conj(G[f][j][k]) --------
__global__ void __launch_bounds__(256, 2) k_fgemm2() {
    __shared__ __align__(16) float2 sS[64 * 34];
    __shared__ __align__(16) float2 sG[64 * 34];

    int bid = blockIdx.x;
    int sel = (bid >= NF * NKC);
    if (sel) bid -= NF * NKC;
    int f  = bid >> 3;
    int kc = bid & 7;

    const float2* S = sel ? g_Sw : g_Sh;
    const float2* G = sel ? g_Gw : g_Gh;
    float2* Cp      = sel ? g_CpW : g_CpH;

    int tid = threadIdx.x;
    int i0 = (tid >> 4) * 2;
    int j0 = (tid & 15) * 2;
    int li = tid >> 3;
    int ls = tid & 7;

    const float2* Sb = S + (size_t)f * BS * KDIM + kc * 512;
    const float2* Gb = G + (size_t)f * BS * KDIM + kc * 512;
    const float4* Sg4 = (const float4*)(Sb + (size_t)li * KDIM);
    const float4* Gg4 = (const float4*)(Gb + (size_t)li * KDIM);

    float c00r = 0, c00i = 0, c01r = 0, c01i = 0;
    float c10r = 0, c10i = 0, c11r = 0, c11i = 0;

    const float4* sS4 = (const float4*)sS;
    const float4* sG4 = (const float4*)sG;
    int ia = i0 >> 1;
    int jb = j0 >> 1;

    for (int kt = 0; kt < 8; kt++) {
        __syncthreads();
#pragma unroll
        for (int u = 0; u < 4; u++) {
            int k4 = ls + u * 8;
            float4 s = Sg4[kt * 32 + k4];
            float4 g = Gg4[kt * 32 + k4];
            sS[(2 * k4)     * 34 + li] = make_float2(s.x, s.y);
            sS[(2 * k4 + 1) * 34 + li] = make_float2(s.z, s.w);
            sG[(2 * k4)     * 34 + li] = make_float2(g.x, g.y);
            sG[(2 * k4 + 1) * 34 + li] = make_float2(g.z, g.w);
        }
        __syncthreads();
#pragma unroll 16
        for (int k = 0; k < 64; k++) {
            float4 a = sS4[k * 17 + ia];
            float4 b = sG4[k * 17 + jb];
            c00r += a.x * b.x + a.y * b.y;  c00i += a.y * b.x - a.x * b.y;
            c01r += a.x * b.z + a.y * b.w;  c01i += a.y * b.z - a.x * b.w;
            c10r += a.z * b.x + a.w * b.y;  c10i += a.w * b.x - a.z * b.y;
            c11r += a.z * b.z + a.w * b.w;  c11i += a.w * b.z - a.z * b.w;
        }
    }
    float2* outp = Cp + ((size_t)kc * NF + f) * BS * BS;
    outp[i0 * 32 + j0]           = make_float2(c00r, c00i);
    outp[i0 * 32 + j0 + 1]       = make_float2(c01r, c01i);
    outp[(i0 + 1) * 32 + j0]     = make_float2(c10r, c10i);
    outp[(i0 + 1) * 32 + j0 + 1] = make_float2(c11r, c11i);
}

// -------- fused inverse transform + first-max argmax + distance --------
__global__ void k_inv(float* __restrict__ out_dist, float* __restrict__ out_orien_f) {
    __shared__ float2 CH[NF], CW[NF];
    __shared__ float valsH[64], valsW[64];
    int i = blockIdx.x >> 5, j = blockIdx.x & 31;
    int s = threadIdx.x;

    if (s < NF) {
        float xr = 0, xi = 0, yr = 0, yi = 0;
#pragma unroll
        for (int kc = 0; kc < NKC; kc++) {
            float2 a = g_CpH[((kc * NF + s) * BS + i) * BS + j];
            float2 b = g_CpW[((kc * NF + s) * BS + i) * BS + j];
            xr += a.x; xi += a.y; yr += b.x; yi += b.y;
        }
        CH[s] = make_float2(xr, xi);
        CW[s] = make_float2(yr, yi);
    }
    __syncthreads();

    float sgn = (s & 1) ? -1.f : 1.f;
    float accH = CH[0].x + sgn * CH[32].x;
    float accW = CW[0].x + sgn * CW[32].x;
#pragma unroll
    for (int f = 1; f < 32; f++) {
        float2 t = g_tw[f * 64 + s];
        accH += 2.f * (CH[f].x * t.x - CH[f].y * t.y);
        accW += 2.f * (CW[f].x * t.x - CW[f].y * t.y);
    }
    valsH[s] = accH;
    valsW[s] = accW;
    __syncthreads();

    if (s == 0) {
        float best = valsH[0]; int bi = 0;
        for (int t = 1; t < 64; t++)
            if (valsH[t] > best) { best = valsH[t]; bi = t; }   // first max
        out_orien_f[i * 32 + j] = (float)bi;
        float q = valsW[bi] * (1.f / 64.f);
        float dot = q / g_norm[i];
        out_dist[j * 32 + i] = 2.f - 2.f * dot;
    }
}

extern "C" void kernel_launch(void* const* d_in, const int* in_sizes, int n_in,
                              void* d_out, int out_size) {
    (void)in_sizes; (void)n_in; (void)out_size;
    const float* sat = (const float*)d_in[0];
    const float* grd = (const float*)d_in[1];
    float* out = (float*)d_out;

    k_init<<<9, 256>>>();

    // All DFT work + passthrough copies + norm partials, one launch.
    k_dft3<<<4096, 256>>>(sat, grd, out);

    k_nred<<<32, 64>>>();

    k_fgemm2<<<2 * NF * NKC, 256>>>();

    float* out_dist  = out + (size_t)2 * SATN;
    float* out_orien = out + (size_t)2 * SATN + 1024;
    k_inv<<<1024, 64>>>(out_dist, out_orien);
}